// round 16
// baseline (speedup 1.0000x reference)
#include <cuda_runtime.h>
#include <cuda_bf16.h>
#include <cuda_fp16.h>
#include <math.h>
#include <stdint.h>

#define NN 100000
#define NN_PAD 100096          // 782 * 128
#define EE 1600000
#define C1 256
#define C3 128
#define NCLS 15
#define BN_EPS 1e-5

// ---------------- scratch (device globals; zero-initialized, no allocation) ----
__device__ float  g_pre  [(size_t)NN_PAD * 256];   // GEMM fp32 out / Zr
__device__ float  g_pre2 [(size_t)NN_PAD * 256];   // L2 post-agg result
__device__ float  g_pre3 [(size_t)NN_PAD * 128];   // L3 post-agg result
__device__ __half g_zl   [(size_t)NN_PAD * 256];   // fp16 Zl (gather operand)
__device__ __half g_meanH[(size_t)NN_PAD * 128];
__device__ __half g_meanL[(size_t)NN_PAD * 128];
__device__ __half g_actH [(size_t)NN_PAD * 256];
__device__ __half g_actL [(size_t)NN_PAD * 256];
__device__ __half g_xH   [(size_t)NN_PAD * 128];   // fp16 hi of x (also L1 gather src)
__device__ __half g_xL   [(size_t)NN_PAD * 128];
__device__ __half g_w    [262144];                 // fp16 weights: W1l|W1r|W2stk|W3stk
__device__ int    g_cnt   [NN];
__device__ int    g_offs  [NN + 1];
__device__ int    g_cursor[NN];
__device__ int    g_bsum  [128];
__device__ int    g_src_sorted[EE];
__device__ double g_acc   [512];
__device__ float  g_scale [256];
__device__ float  g_shift [256];
__device__ unsigned g_ctr[4];                      // last-block counters (self-resetting)
__device__ int    g_is64;

// ---------------- PTX helpers ---------------------------------------------------
__device__ __forceinline__ uint32_t smem_u32(const void* p) {
    uint32_t a;
    asm("{ .reg .u64 t; cvta.to.shared.u64 t, %1; cvt.u32.u64 %0, t; }" : "=r"(a) : "l"(p));
    return a;
}
#define CP_ASYNC16(sa, g) \
    asm volatile("cp.async.cg.shared.global [%0], [%1], 16;" :: "r"(sa), "l"(g) : "memory")
#define CP_COMMIT() asm volatile("cp.async.commit_group;" ::: "memory")
#define LDSM4(r, a) \
    asm volatile("ldmatrix.sync.aligned.m8n8.x4.shared.b16 {%0,%1,%2,%3}, [%4];" \
        : "=r"((r)[0]), "=r"((r)[1]), "=r"((r)[2]), "=r"((r)[3]) : "r"(a))
#define MMAF16(d, a, b) \
    asm volatile("mma.sync.aligned.m16n8k16.row.col.f32.f16.f16.f32 " \
        "{%0,%1,%2,%3}, {%4,%5,%6,%7}, {%8,%9}, {%0,%1,%2,%3};" \
        : "+f"((d)[0]), "+f"((d)[1]), "+f"((d)[2]), "+f"((d)[3]) \
        : "r"((a)[0]), "r"((a)[1]), "r"((a)[2]), "r"((a)[3]), "r"((b)[0]), "r"((b)[1]))

// DP finalize for column c (single executing block only)
__device__ __forceinline__ void finalize_col(int c, const float* g, const float* b) {
    double mu  = g_acc[c] / (double)NN;
    double var = g_acc[256 + c] / (double)NN - mu * mu;
    double rs  = 1.0 / sqrt(var + BN_EPS);
    double sc  = (double)g[c] * rs;
    g_scale[c] = (float)sc;
    g_shift[c] = (float)((double)b[c] - mu * sc);
    g_acc[c] = 0.0;
    g_acc[256 + c] = 0.0;
}

// ---------------- small utility kernels --------------------------------------
__global__ void k_zero_cnt(const void* edges) {
    int i = blockIdx.x * blockDim.x + threadIdx.x;
    if (i < NN) g_cnt[i] = 0;
    if (i == 0) {
        const int* p = (const int*)edges;
        int ok = 1;
        for (int j = 0; j < 64; j++)
            if (p[2 * j + 1] != 0) ok = 0;
        g_is64 = ok;
    }
}
// merged conversions: blocks [0,1024) weights -> fp16; rest x -> fp16 hi/lo
__global__ void k_convert(const float* __restrict__ w1l, const float* __restrict__ w1r,
                          const float* __restrict__ w2l, const float* __restrict__ w2r,
                          const float* __restrict__ w3l, const float* __restrict__ w3r,
                          __half* __restrict__ wbuf, const float* __restrict__ x,
                          __half* __restrict__ xh, __half* __restrict__ xl) {
    if (blockIdx.x < 1024) {
        int i = blockIdx.x * 256 + threadIdx.x;   // 0..262143
        float v;
        if      (i <  32768) v = w1l[i];
        else if (i <  65536) v = w1r[i -  32768];
        else if (i < 131072) v = w2l[i -  65536];
        else if (i < 196608) v = w2r[i - 131072];
        else if (i < 229376) v = w3l[i - 196608];
        else                 v = w3r[i - 229376];
        wbuf[i] = __float2half_rn(v);
    } else {
        int i = (blockIdx.x - 1024) * 256 + threadIdx.x;
        if (i < NN * 128) {
            float v = x[i];
            __half hh = __float2half_rn(v);
            xh[i] = hh;
            xl[i] = __float2half_rn(v - __half2float(hh));
        }
    }
}

// ---------------- CSR construction --------------------------------------------
__global__ void k_hist(const void* edges) {
    int e = blockIdx.x * blockDim.x + threadIdx.x;
    if (e >= EE) return;
    int d;
    if (g_is64) d = (int)((const long long*)edges)[EE + e];
    else        d = ((const int*)edges)[EE + e];
    atomicAdd(&g_cnt[d], 1);
}
__global__ void k_scan1() {
    __shared__ int sh[1024];
    int i = blockIdx.x * 1024 + threadIdx.x;
    int v = (i < NN) ? g_cnt[i] : 0;
    sh[threadIdx.x] = v;
    __syncthreads();
    for (int off = 1; off < 1024; off <<= 1) {
        int t = (threadIdx.x >= off) ? sh[threadIdx.x - off] : 0;
        __syncthreads();
        sh[threadIdx.x] += t;
        __syncthreads();
    }
    if (i < NN) g_offs[i] = sh[threadIdx.x] - v;
    if (threadIdx.x == 1023) g_bsum[blockIdx.x] = sh[1023];
}
// scan of block sums (redundant per block, cheap int ops) + apply offsets
__global__ void k_scan3() {
    __shared__ int sh[128], sh2[128];
    int t = threadIdx.x;  // 256 threads
    const int nb = (NN + 1023) / 1024;
    if (t < 128) sh[t] = (t < nb) ? g_bsum[t] : 0;
    __syncthreads();
    for (int off = 1; off < 128; off <<= 1) {
        int tv = (t < 128 && t >= off) ? sh[t - off] : 0;
        __syncthreads();
        if (t < 128) sh[t] += tv;
        __syncthreads();
    }
    if (t < 128) {
        int v = (t < nb) ? g_bsum[t] : 0;
        sh2[t] = sh[t] - v;   // exclusive
    }
    __syncthreads();
    int i = blockIdx.x * blockDim.x + t;
    if (i < NN) {
        int off = g_offs[i] + sh2[i >> 10];
        g_offs[i]   = off;
        g_cursor[i] = off;
    }
    if (i == 0) g_offs[NN] = EE;
}
__global__ void k_fill(const void* edges) {
    int e = blockIdx.x * blockDim.x + threadIdx.x;
    if (e >= EE) return;
    int s, d;
    if (g_is64) {
        const long long* p = (const long long*)edges;
        s = (int)p[e]; d = (int)p[EE + e];
    } else {
        const int* p = (const int*)edges;
        s = p[e]; d = p[EE + e];
    }
    int pos = atomicAdd(&g_cursor[d], 1);
    g_src_sorted[pos] = s;
}

// ---------------- layer-1 aggregation: gather fp16 xH + fp16 hi/lo split --------
__global__ __launch_bounds__(128) void k_agg_x(
    const __half* __restrict__ xf, __half* __restrict__ mh, __half* __restrict__ ml)
{
    int tid = threadIdx.x, group = tid >> 4, lane = tid & 15;
    int node = blockIdx.x * 8 + group;
    if (node >= NN) return;
    int beg = g_offs[node], end = g_offs[node + 1];
    float acc[8] = {};
    int e = beg;
    for (; e + 1 < end; e += 2) {
        uint4 v0 = ((const uint4*)(xf + (size_t)g_src_sorted[e] * 128))[lane];
        uint4 v1 = ((const uint4*)(xf + (size_t)g_src_sorted[e + 1] * 128))[lane];
        const __half2* h0 = (const __half2*)&v0;
        const __half2* h1 = (const __half2*)&v1;
#pragma unroll
        for (int j = 0; j < 4; j++) {
            float2 f0 = __half22float2(h0[j]);
            float2 f1 = __half22float2(h1[j]);
            acc[2 * j]     += f0.x + f1.x;
            acc[2 * j + 1] += f0.y + f1.y;
        }
    }
    if (e < end) {
        uint4 v0 = ((const uint4*)(xf + (size_t)g_src_sorted[e] * 128))[lane];
        const __half2* h0 = (const __half2*)&v0;
#pragma unroll
        for (int j = 0; j < 4; j++) {
            float2 f0 = __half22float2(h0[j]);
            acc[2 * j] += f0.x; acc[2 * j + 1] += f0.y;
        }
    }
    float inv = 1.0f / fmaxf((float)(end - beg), 1.0f);
    __half hv[8], lv[8];
#pragma unroll
    for (int j = 0; j < 8; j++) {
        float o = acc[j] * inv;
        hv[j] = __float2half_rn(o);
        lv[j] = __float2half_rn(o - __half2float(hv[j]));
    }
    ((uint4*)(mh + (size_t)node * 128))[lane] = *(uint4*)hv;
    ((uint4*)(ml + (size_t)node * 128))[lane] = *(uint4*)lv;
}

// ---------------- post-aggregation (fp16 Zl gather) + fused BN stats + finalize --
__global__ __launch_bounds__(128) void k_agg_post2(
    const __half* __restrict__ zl, const float* __restrict__ zr, float* __restrict__ out,
    const float* __restrict__ gv, const float* __restrict__ bv)
{
    __shared__ float ss[256], sq[256];
    __shared__ bool lastBlk;
    int tid = threadIdx.x;
    ss[tid] = 0.f; sq[tid] = 0.f; ss[tid + 128] = 0.f; sq[tid + 128] = 0.f;
    __syncthreads();
    int group = tid >> 5, lane = tid & 31;
    float ts[8] = {}, tq[8] = {};
    for (int node = blockIdx.x * 4 + group; node < NN; node += gridDim.x * 4) {
        int beg = g_offs[node], end = g_offs[node + 1];
        float acc[8] = {};
        int e = beg;
        for (; e + 1 < end; e += 2) {
            uint4 v0 = ((const uint4*)(zl + (size_t)g_src_sorted[e] * 256))[lane];
            uint4 v1 = ((const uint4*)(zl + (size_t)g_src_sorted[e + 1] * 256))[lane];
            const __half2* h0 = (const __half2*)&v0;
            const __half2* h1 = (const __half2*)&v1;
#pragma unroll
            for (int j = 0; j < 4; j++) {
                float2 f0 = __half22float2(h0[j]);
                float2 f1 = __half22float2(h1[j]);
                acc[2 * j]     += f0.x + f1.x;
                acc[2 * j + 1] += f0.y + f1.y;
            }
        }
        if (e < end) {
            uint4 v0 = ((const uint4*)(zl + (size_t)g_src_sorted[e] * 256))[lane];
            const __half2* h0 = (const __half2*)&v0;
#pragma unroll
            for (int j = 0; j < 4; j++) {
                float2 f0 = __half22float2(h0[j]);
                acc[2 * j] += f0.x; acc[2 * j + 1] += f0.y;
            }
        }
        float inv = 1.0f / fmaxf((float)(end - beg), 1.0f);
        float4 r0 = ((const float4*)(zr + (size_t)node * 256))[2 * lane];
        float4 r1 = ((const float4*)(zr + (size_t)node * 256))[2 * lane + 1];
        float o[8];
        o[0] = acc[0] * inv + r0.x; o[1] = acc[1] * inv + r0.y;
        o[2] = acc[2] * inv + r0.z; o[3] = acc[3] * inv + r0.w;
        o[4] = acc[4] * inv + r1.x; o[5] = acc[5] * inv + r1.y;
        o[6] = acc[6] * inv + r1.z; o[7] = acc[7] * inv + r1.w;
        ((float4*)(out + (size_t)node * 256))[2 * lane]     = make_float4(o[0], o[1], o[2], o[3]);
        ((float4*)(out + (size_t)node * 256))[2 * lane + 1] = make_float4(o[4], o[5], o[6], o[7]);
#pragma unroll
        for (int j = 0; j < 8; j++) { ts[j] += o[j]; tq[j] += o[j] * o[j]; }
    }
#pragma unroll
    for (int j = 0; j < 8; j++) {
        atomicAdd(&ss[lane * 8 + j], ts[j]);
        atomicAdd(&sq[lane * 8 + j], tq[j]);
    }
    __syncthreads();
    atomicAdd(&g_acc[tid],             (double)ss[tid]);
    atomicAdd(&g_acc[tid + 128],       (double)ss[tid + 128]);
    atomicAdd(&g_acc[256 + tid],       (double)sq[tid]);
    atomicAdd(&g_acc[256 + tid + 128], (double)sq[tid + 128]);
    __threadfence();
    __syncthreads();
    if (tid == 0)
        lastBlk = (atomicAdd(&g_ctr[1], 1u) == gridDim.x - 1);
    __syncthreads();
    if (lastBlk) {
        finalize_col(tid, gv, bv);
        finalize_col(tid + 128, gv, bv);
        if (tid == 0) g_ctr[1] = 0;
    }
}

__global__ __launch_bounds__(128) void k_agg_post3(
    const __half* __restrict__ zl, const float* __restrict__ zr, float* __restrict__ out,
    const float* __restrict__ gv, const float* __restrict__ bv)
{
    __shared__ float ss[128], sq[128];
    __shared__ bool lastBlk;
    int tid = threadIdx.x;
    ss[tid] = 0.f; sq[tid] = 0.f;
    __syncthreads();
    int group = tid >> 4, lane = tid & 15;
    float ts[8] = {}, tq[8] = {};
    for (int node = blockIdx.x * 8 + group; node < NN; node += gridDim.x * 8) {
        int beg = g_offs[node], end = g_offs[node + 1];
        float acc[8] = {};
        int e = beg;
        for (; e + 1 < end; e += 2) {
            uint4 v0 = ((const uint4*)(zl + (size_t)g_src_sorted[e] * 128))[lane];
            uint4 v1 = ((const uint4*)(zl + (size_t)g_src_sorted[e + 1] * 128))[lane];
            const __half2* h0 = (const __half2*)&v0;
            const __half2* h1 = (const __half2*)&v1;
#pragma unroll
            for (int j = 0; j < 4; j++) {
                float2 f0 = __half22float2(h0[j]);
                float2 f1 = __half22float2(h1[j]);
                acc[2 * j]     += f0.x + f1.x;
                acc[2 * j + 1] += f0.y + f1.y;
            }
        }
        if (e < end) {
            uint4 v0 = ((const uint4*)(zl + (size_t)g_src_sorted[e] * 128))[lane];
            const __half2* h0 = (const __half2*)&v0;
#pragma unroll
            for (int j = 0; j < 4; j++) {
                float2 f0 = __half22float2(h0[j]);
                acc[2 * j] += f0.x; acc[2 * j + 1] += f0.y;
            }
        }
        float inv = 1.0f / fmaxf((float)(end - beg), 1.0f);
        float4 r0 = ((const float4*)(zr + (size_t)node * 128))[2 * lane];
        float4 r1 = ((const float4*)(zr + (size_t)node * 128))[2 * lane + 1];
        float o[8];
        o[0] = acc[0] * inv + r0.x; o[1] = acc[1] * inv + r0.y;
        o[2] = acc[2] * inv + r0.z; o[3] = acc[3] * inv + r0.w;
        o[4] = acc[4] * inv + r1.x; o[5] = acc[5] * inv + r1.y;
        o[6] = acc[6] * inv + r1.z; o[7] = acc[7] * inv + r1.w;
        ((float4*)(out + (size_t)node * 128))[2 * lane]     = make_float4(o[0], o[1], o[2], o[3]);
        ((float4*)(out + (size_t)node * 128))[2 * lane + 1] = make_float4(o[4], o[5], o[6], o[7]);
#pragma unroll
        for (int j = 0; j < 8; j++) { ts[j] += o[j]; tq[j] += o[j] * o[j]; }
    }
#pragma unroll
    for (int j = 0; j < 8; j++) {
        atomicAdd(&ss[lane * 8 + j], ts[j]);
        atomicAdd(&sq[lane * 8 + j], tq[j]);
    }
    __syncthreads();
    atomicAdd(&g_acc[tid],       (double)ss[tid]);
    atomicAdd(&g_acc[256 + tid], (double)sq[tid]);
    __threadfence();
    __syncthreads();
    if (tid == 0)
        lastBlk = (atomicAdd(&g_ctr[2], 1u) == gridDim.x - 1);
    __syncthreads();
    if (lastBlk) {
        finalize_col(tid, gv, bv);
        if (tid == 0) g_ctr[2] = 0;
    }
}

// ---------------- fp16 2-term mma.sync GEMM; 3-stage pipeline ------------------
// MODE 0: L1 dual (NSEG=4) + fused BN stats + last-block finalize
// MODE 1: L2 (x<2 -> Z); MODE 2: L3 (x==0 -> Z)
template <int DI, int NSEG, int MODE>
__global__ __launch_bounds__(256) void k_gemm_mma(
    const __half* __restrict__ A1h, const __half* __restrict__ A1l,
    const __half* __restrict__ A2h, const __half* __restrict__ A2l,
    const __half* __restrict__ B1, const __half* __restrict__ B2,
    float* __restrict__ C, __half* __restrict__ Z,
    const float* __restrict__ gv, const float* __restrict__ bv)
{
    constexpr int CH_PER_SEG = DI / 32;
    constexpr int NCH = NSEG * CH_PER_SEG;
    constexpr uint32_t STG = 20480;
    extern __shared__ __align__(128) char smem[];
    __shared__ float cs[128], cq[128];
    __shared__ bool lastBlk;
    const uint32_t sbase = smem_u32(smem);
    const int tid = threadIdx.x;
    const int wid = tid >> 5, lane = tid & 31;
    const int wr = wid >> 2, wcn = wid & 3;
    const int rowBase = blockIdx.y * 128;   // M-tile (slow)
    const int colBase = blockIdx.x * 128;   // N-tile (fast -> A reuse)

    const __half* Asrc[4] = {A1h, A1l, A2h, A2l};
    const __half* Bsrc[4] = {B1, B1, B2, B2};

    const int lrow = tid >> 2;
    const int lcg  = tid & 3;
    const uint32_t sA0 = sbase + lrow * 80 + lcg * 16;
    const uint32_t sB0 = sbase + 10240 + lrow * 80 + lcg * 16;

    auto load = [&](int c) {
        const int s = c % 3;
        const int seg = c / CH_PER_SEG;
        const int kk = (c % CH_PER_SEG) * 32;
        const __half* Ap = Asrc[seg] + (size_t)rowBase * DI + kk + lcg * 8;
        const __half* Bp = Bsrc[seg] + (size_t)colBase * DI + kk + lcg * 8;
        const uint32_t so = s * STG;
        CP_ASYNC16(sA0 + so,        Ap + (size_t)lrow * DI);
        CP_ASYNC16(sA0 + so + 5120, Ap + (size_t)(lrow + 64) * DI);
        CP_ASYNC16(sB0 + so,        Bp + (size_t)lrow * DI);
        CP_ASYNC16(sB0 + so + 5120, Bp + (size_t)(lrow + 64) * DI);
        CP_COMMIT();
    };

    float acc[4][4][4] = {};
    const uint32_t aAddr = sbase + (wr * 64 + (lane & 15)) * 80 + (lane >> 4) * 16;
    const uint32_t bAddr = sbase + 10240 +
        (wcn * 32 + (lane & 7) + ((lane >> 4) << 3)) * 80 + ((lane >> 3) & 1) * 16;

    load(0);
    load(1);
    for (int c = 0; c < NCH; c++) {
        if (c + 1 < NCH)
            asm volatile("cp.async.wait_group 1;" ::: "memory");
        else
            asm volatile("cp.async.wait_group 0;" ::: "memory");
        __syncthreads();
        // all warps are past reading stage (c+2)%3 (read at iter c-1) -> safe to refill
        if (c + 2 < NCH) load(c + 2);
        const uint32_t so = (uint32_t)(c % 3) * STG;
#pragma unroll
        for (int kb = 0; kb < 2; kb++) {
            uint32_t afr[4][4], bfr[4][2];
#pragma unroll
            for (int mt = 0; mt < 4; mt++)
                LDSM4(afr[mt], aAddr + so + mt * (16 * 80) + kb * 32);
#pragma unroll
            for (int ntp = 0; ntp < 2; ntp++) {
                uint32_t r[4];
                LDSM4(r, bAddr + so + ntp * (16 * 80) + kb * 32);
                bfr[ntp * 2][0] = r[0]; bfr[ntp * 2][1] = r[1];
                bfr[ntp * 2 + 1][0] = r[2]; bfr[ntp * 2 + 1][1] = r[3];
            }
#pragma unroll
            for (int mt = 0; mt < 4; mt++)
#pragma unroll
                for (int nt = 0; nt < 4; nt++)
                    MMAF16(acc[mt][nt], afr[mt], bfr[nt]);
        }
    }

    // epilogue
    constexpr int STRIDE = (MODE == 2) ? 128 : 256;
    const bool isZ = (MODE == 1) ? (blockIdx.x < 2) : (MODE == 2 ? (blockIdx.x == 0) : false);
    const int cadj = (MODE == 0 || isZ) ? colBase : colBase - STRIDE;
#pragma unroll
    for (int mt = 0; mt < 4; mt++) {
        const int r0 = rowBase + wr * 64 + mt * 16 + (lane >> 2);
#pragma unroll
        for (int nt = 0; nt < 4; nt++) {
            const int cc = cadj + wcn * 32 + nt * 8 + (lane & 3) * 2;
            if (MODE != 0 && isZ) {
                if (r0 < NN)
                    *(__half2*)(Z + (size_t)r0 * STRIDE + cc) =
                        __floats2half2_rn(acc[mt][nt][0], acc[mt][nt][1]);
                if (r0 + 8 < NN)
                    *(__half2*)(Z + (size_t)(r0 + 8) * STRIDE + cc) =
                        __floats2half2_rn(acc[mt][nt][2], acc[mt][nt][3]);
            } else {
                if (r0 < NN)
                    *(float2*)(C + (size_t)r0 * STRIDE + cc) =
                        make_float2(acc[mt][nt][0], acc[mt][nt][1]);
                if (r0 + 8 < NN)
                    *(float2*)(C + (size_t)(r0 + 8) * STRIDE + cc) =
                        make_float2(acc[mt][nt][2], acc[mt][nt][3]);
            }
        }
    }

    if (MODE == 0) {
        if (tid < 128) { cs[tid] = 0.f; cq[tid] = 0.f; }
        __syncthreads();
#pragma unroll
        for (int nt = 0; nt < 4; nt++) {
            float s0 = 0.f, q0 = 0.f, s1 = 0.f, q1 = 0.f;
#pragma unroll
            for (int mt = 0; mt < 4; mt++) {
                float a0 = acc[mt][nt][0], a1 = acc[mt][nt][1];
                float a2 = acc[mt][nt][2], a3 = acc[mt][nt][3];
                s0 += a0 + a2; q0 += a0 * a0 + a2 * a2;
                s1 += a1 + a3; q1 += a1 * a1 + a3 * a3;
            }
            int cc = wcn * 32 + nt * 8 + (lane & 3) * 2;
            atomicAdd(&cs[cc], s0);     atomicAdd(&cq[cc], q0);
            atomicAdd(&cs[cc + 1], s1); atomicAdd(&cq[cc + 1], q1);
        }
        __syncthreads();
        if (tid < 128) {
            atomicAdd(&g_acc[colBase + tid],       (double)cs[tid]);
            atomicAdd(&g_acc[256 + colBase + tid], (double)cq[tid]);
        }
        __threadfence();
        __syncthreads();
        if (tid == 0)
            lastBlk = (atomicAdd(&g_ctr[0], 1u) == gridDim.x * gridDim.y - 1);
        __syncthreads();
        if (lastBlk) {
            finalize_col(tid, gv, bv);   // 256 threads cover D=256
            if (tid == 0) g_ctr[0] = 0;
        }
    }
}

// BN + ReLU -> fp16 hi/lo
template <int D>
__global__ void k_bn_hl(const float* __restrict__ in,
                        __half* __restrict__ outH, __half* __restrict__ outL) {
    int i = blockIdx.x * blockDim.x + threadIdx.x;
    int total4 = NN * D / 4;
    if (i >= total4) return;
    int c4 = (i & (D / 4 - 1)) * 4;
    float4 v  = ((const float4*)in)[i];
    float4 sc = *(const float4*)&g_scale[c4];
    float4 sh = *(const float4*)&g_shift[c4];
    float o[4];
    o[0] = fmaxf(v.x * sc.x + sh.x, 0.f);
    o[1] = fmaxf(v.y * sc.y + sh.y, 0.f);
    o[2] = fmaxf(v.z * sc.z + sh.z, 0.f);
    o[3] = fmaxf(v.w * sc.w + sh.w, 0.f);
    __half hv[4], lv[4];
#pragma unroll
    for (int q = 0; q < 4; q++) {
        hv[q] = __float2half_rn(o[q]);
        lv[q] = __float2half_rn(o[q] - __half2float(hv[q]));
    }
    *(uint2*)(outH + (size_t)i * 4) = *(uint2*)hv;
    *(uint2*)(outL + (size_t)i * 4) = *(uint2*)lv;
}

// fused BN + ReLU + classifier (layer 3): pre3 [N,128] -> out [N,15]
__global__ __launch_bounds__(256) void k_bn_cls(
    const float* __restrict__ pre3, const float* __restrict__ wc,
    const float* __restrict__ bc, float* __restrict__ out)
{
    __shared__ float4 wsh[NCLS * 32];
    __shared__ float  bsh[NCLS];
    int tid = threadIdx.x;
    for (int i = tid; i < NCLS * 32; i += 256) wsh[i] = ((const float4*)wc)[i];
    if (tid < NCLS) bsh[tid] = bc[tid];
    __syncthreads();
    int warp = tid >> 5, lane = tid & 31;
    int row = blockIdx.x * 8 + warp;
    if (row >= NN) return;
    float4 v  = ((const float4*)pre3)[(size_t)row * 32 + lane];
    float4 sc = *(const float4*)&g_scale[lane * 4];
    float4 sh = *(const float4*)&g_shift[lane * 4];
    float4 hv;
    hv.x = fmaxf(v.x * sc.x + sh.x, 0.f);
    hv.y = fmaxf(v.y * sc.y + sh.y, 0.f);
    hv.z = fmaxf(v.z * sc.z + sh.z, 0.f);
    hv.w = fmaxf(v.w * sc.w + sh.w, 0.f);
#pragma unroll
    for (int j = 0; j < NCLS; j++) {
        float4 w = wsh[j * 32 + lane];
        float p = hv.x * w.x + hv.y * w.y + hv.z * w.z + hv.w * w.w;
#pragma unroll
        for (int o = 16; o > 0; o >>= 1) p += __shfl_xor_sync(0xFFFFFFFFu, p, o);
        if (lane == 0) out[(size_t)row * NCLS + j] = p + bsh[j];
    }
}

// ---------------- driver --------------------------------------------------------
extern "C" void kernel_launch(void* const* d_in, const int* in_sizes, int n_in,
                              void* d_out, int out_size)
{
    const float* x     = (const float*)d_in[0];
    const void*  edges = d_in[1];
    const float* w1_l = (const float*)d_in[2];
    const float* w1_r = (const float*)d_in[4];
    const float* g1   = (const float*)d_in[5];
    const float* be1  = (const float*)d_in[6];
    const float* w2_l = (const float*)d_in[7];
    const float* w2_r = (const float*)d_in[9];
    const float* g2   = (const float*)d_in[10];
    const float* be2  = (const float*)d_in[11];
    const float* w3_l = (const float*)d_in[12];
    const float* w3_r = (const float*)d_in[14];
    const float* g3   = (const float*)d_in[15];
    const float* be3  = (const float*)d_in[16];
    const float* wc   = (const float*)d_in[17];
    const float* bc   = (const float*)d_in[18];
    float* out = (float*)d_out;

    static float *pre = nullptr, *pre2 = nullptr, *pre3 = nullptr;
    static __half *zl, *meanH, *meanL, *actH, *actL, *xH, *xL, *wbuf;
    const int GSMEM = 3 * 20480;  // 61,440 B dynamic
    if (!pre) {
        cudaGetSymbolAddress((void**)&pre,   g_pre);
        cudaGetSymbolAddress((void**)&pre2,  g_pre2);
        cudaGetSymbolAddress((void**)&pre3,  g_pre3);
        cudaGetSymbolAddress((void**)&zl,    g_zl);
        cudaGetSymbolAddress((void**)&meanH, g_meanH);
        cudaGetSymbolAddress((void**)&meanL, g_meanL);
        cudaGetSymbolAddress((void**)&actH,  g_actH);
        cudaGetSymbolAddress((void**)&actL,  g_actL);
        cudaGetSymbolAddress((void**)&xH,    g_xH);
        cudaGetSymbolAddress((void**)&xL,    g_xL);
        cudaGetSymbolAddress((void**)&wbuf,  g_w);
        cudaFuncSetAttribute(k_gemm_mma<128, 4, 0>,
                             cudaFuncAttributeMaxDynamicSharedMemorySize, GSMEM);
        cudaFuncSetAttribute(k_gemm_mma<256, 2, 1>,
                             cudaFuncAttributeMaxDynamicSharedMemorySize, GSMEM);
        cudaFuncSetAttribute(k_gemm_mma<256, 2, 2>,
                             cudaFuncAttributeMaxDynamicSharedMemorySize, GSMEM);
    }
    // weight layout (fp16): W1l@0, W1r@32768, W2stk@65536, W3stk@196608
    __half* W1l = wbuf;
    __half* W1r = wbuf + 32768;
    __half* W2  = wbuf + 65536;
    __half* W3  = wbuf + 196608;

    const int EB = (EE + 255) / 256;
    const int NB = (NN + 255) / 256;

    // ---- CSR build ----
    k_zero_cnt<<<NB, 256>>>(edges);
    k_hist<<<EB, 256>>>(edges);
    k_scan1<<<(NN + 1023) / 1024, 1024>>>();
    k_scan3<<<NB, 256>>>();
    k_fill<<<EB, 256>>>(edges);

    // ---- weight + x conversions (fp16), single launch ----
    k_convert<<<1024 + (NN * 128 + 255) / 256, 256>>>(w1_l, w1_r, w2_l, w2_r, w3_l, w3_r,
                                                      wbuf, x, xH, xL);

    const int MT = NN_PAD / 128;  // 782

    // ---- layer 1: pre-agg (fp16 gather) + dual GEMM (stats + finalize fused) ----
    k_agg_x<<<(NN + 7) / 8, 128>>>(xH, meanH, meanL);
    k_gemm_mma<128, 4, 0><<<dim3(2, MT), 256, GSMEM>>>(meanH, meanL, xH, xL,
                                                       W1l, W1r, pre, nullptr, g1, be1);
    k_bn_hl<C1><<<(NN * C1 / 4 + 255) / 256, 256>>>(pre, actH, actL);

    // ---- layer 2: single-A GEMM (DO=512) -> fp16 Zl + fp32 Zr; post-agg+finalize --
    k_gemm_mma<256, 2, 1><<<dim3(4, MT), 256, GSMEM>>>(actH, actL, nullptr, nullptr,
                                                       W2, nullptr, pre, zl, nullptr, nullptr);
    k_agg_post2<<<1024, 128>>>(zl, pre, pre2, g2, be2);
    k_bn_hl<C1><<<(NN * C1 / 4 + 255) / 256, 256>>>(pre2, actH, actL);

    // ---- layer 3: single-A GEMM (DO=256) -> fp16 Zl + fp32 Zr; post-agg+finalize --
    k_gemm_mma<256, 2, 2><<<dim3(2, MT), 256, GSMEM>>>(actH, actL, nullptr, nullptr,
                                                       W3, nullptr, pre, zl, nullptr, nullptr);
    k_agg_post3<<<1024, 128>>>(zl, pre, pre3, g3, be3);

    // ---- fused BN + ReLU + classifier ----
    k_bn_cls<<<(NN + 7) / 8, 256>>>(pre3, wc, bc, out);
}

// round 17
// speedup vs baseline: 1.0095x; 1.0095x over previous
#include <cuda_runtime.h>
#include <cuda_bf16.h>
#include <cuda_fp16.h>
#include <math.h>
#include <stdint.h>

#define NN 100000
#define NN_PAD 100096          // 782 * 128
#define EE 1600000
#define C1 256
#define C3 128
#define NCLS 15
#define BN_EPS 1e-5

// ---------------- scratch (device globals; zero-initialized, no allocation) ----
__device__ float  g_pre  [(size_t)NN_PAD * 256];   // GEMM fp32 out / Zr
__device__ float  g_pre2 [(size_t)NN_PAD * 256];   // L2 post-agg result
__device__ float  g_pre3 [(size_t)NN_PAD * 128];   // L3 post-agg result
__device__ __half g_zl   [(size_t)NN_PAD * 256];   // fp16 Zl (gather operand)
__device__ __half g_meanH[(size_t)NN_PAD * 128];
__device__ __half g_meanL[(size_t)NN_PAD * 128];
__device__ __half g_actH [(size_t)NN_PAD * 256];
__device__ __half g_actL [(size_t)NN_PAD * 256];
__device__ __half g_xH   [(size_t)NN_PAD * 128];   // fp16 hi of x (also L1 gather src)
__device__ __half g_xL   [(size_t)NN_PAD * 128];
__device__ __half g_w    [262144];                 // fp16 weights: W1l|W1r|W2stk|W3stk
__device__ int    g_cnt   [NN];
__device__ int    g_offs  [NN + 1];
__device__ int    g_cursor[NN];
__device__ int    g_bsum  [128];
__device__ int    g_src_sorted[EE];
__device__ double g_acc   [512];
__device__ float  g_scale [256];
__device__ float  g_shift [256];
__device__ int    g_is64;

// ---------------- PTX helpers ---------------------------------------------------
__device__ __forceinline__ uint32_t smem_u32(const void* p) {
    uint32_t a;
    asm("{ .reg .u64 t; cvta.to.shared.u64 t, %1; cvt.u32.u64 %0, t; }" : "=r"(a) : "l"(p));
    return a;
}
#define CP_ASYNC16(sa, g) \
    asm volatile("cp.async.cg.shared.global [%0], [%1], 16;" :: "r"(sa), "l"(g) : "memory")
#define CP_COMMIT() asm volatile("cp.async.commit_group;" ::: "memory")
#define LDSM4(r, a) \
    asm volatile("ldmatrix.sync.aligned.m8n8.x4.shared.b16 {%0,%1,%2,%3}, [%4];" \
        : "=r"((r)[0]), "=r"((r)[1]), "=r"((r)[2]), "=r"((r)[3]) : "r"(a))
#define MMAF16(d, a, b) \
    asm volatile("mma.sync.aligned.m16n8k16.row.col.f32.f16.f16.f32 " \
        "{%0,%1,%2,%3}, {%4,%5,%6,%7}, {%8,%9}, {%0,%1,%2,%3};" \
        : "+f"((d)[0]), "+f"((d)[1]), "+f"((d)[2]), "+f"((d)[3]) \
        : "r"((a)[0]), "r"((a)[1]), "r"((a)[2]), "r"((a)[3]), "r"((b)[0]), "r"((b)[1]))

// ---------------- small utility kernels --------------------------------------
__global__ void k_zero_cnt(const void* edges) {
    int i = blockIdx.x * blockDim.x + threadIdx.x;
    if (i < NN) g_cnt[i] = 0;
    if (i == 0) {
        const int* p = (const int*)edges;
        int ok = 1;
        for (int j = 0; j < 64; j++)
            if (p[2 * j + 1] != 0) ok = 0;
        g_is64 = ok;
    }
}
// merged conversions: blocks [0,1024) weights -> fp16; rest x -> fp16 hi/lo
__global__ void k_convert(const float* __restrict__ w1l, const float* __restrict__ w1r,
                          const float* __restrict__ w2l, const float* __restrict__ w2r,
                          const float* __restrict__ w3l, const float* __restrict__ w3r,
                          __half* __restrict__ wbuf, const float* __restrict__ x,
                          __half* __restrict__ xh, __half* __restrict__ xl) {
    if (blockIdx.x < 1024) {
        int i = blockIdx.x * 256 + threadIdx.x;   // 0..262143
        float v;
        if      (i <  32768) v = w1l[i];
        else if (i <  65536) v = w1r[i -  32768];
        else if (i < 131072) v = w2l[i -  65536];
        else if (i < 196608) v = w2r[i - 131072];
        else if (i < 229376) v = w3l[i - 196608];
        else                 v = w3r[i - 229376];
        wbuf[i] = __float2half_rn(v);
    } else {
        int i = (blockIdx.x - 1024) * 256 + threadIdx.x;
        if (i < NN * 128) {
            float v = x[i];
            __half hh = __float2half_rn(v);
            xh[i] = hh;
            xl[i] = __float2half_rn(v - __half2float(hh));
        }
    }
}

// ---------------- CSR construction --------------------------------------------
__global__ void k_hist(const void* edges) {
    int e = blockIdx.x * blockDim.x + threadIdx.x;
    if (e >= EE) return;
    int d;
    if (g_is64) d = (int)((const long long*)edges)[EE + e];
    else        d = ((const int*)edges)[EE + e];
    atomicAdd(&g_cnt[d], 1);
}
__global__ void k_scan1() {
    __shared__ int sh[1024];
    int i = blockIdx.x * 1024 + threadIdx.x;
    int v = (i < NN) ? g_cnt[i] : 0;
    sh[threadIdx.x] = v;
    __syncthreads();
    for (int off = 1; off < 1024; off <<= 1) {
        int t = (threadIdx.x >= off) ? sh[threadIdx.x - off] : 0;
        __syncthreads();
        sh[threadIdx.x] += t;
        __syncthreads();
    }
    if (i < NN) g_offs[i] = sh[threadIdx.x] - v;
    if (threadIdx.x == 1023) g_bsum[blockIdx.x] = sh[1023];
}
// per-block redundant scan of block sums (cheap int ops) + apply offsets
__global__ void k_scan3() {
    __shared__ int sh[128], sh2[128];
    int t = threadIdx.x;  // 256 threads
    const int nb = (NN + 1023) / 1024;
    if (t < 128) sh[t] = (t < nb) ? g_bsum[t] : 0;
    __syncthreads();
    for (int off = 1; off < 128; off <<= 1) {
        int tv = (t < 128 && t >= off) ? sh[t - off] : 0;
        __syncthreads();
        if (t < 128) sh[t] += tv;
        __syncthreads();
    }
    if (t < 128) {
        int v = (t < nb) ? g_bsum[t] : 0;
        sh2[t] = sh[t] - v;   // exclusive
    }
    __syncthreads();
    int i = blockIdx.x * blockDim.x + t;
    if (i < NN) {
        int off = g_offs[i] + sh2[i >> 10];
        g_offs[i]   = off;
        g_cursor[i] = off;
    }
    if (i == 0) g_offs[NN] = EE;
}
__global__ void k_fill(const void* edges) {
    int e = blockIdx.x * blockDim.x + threadIdx.x;
    if (e >= EE) return;
    int s, d;
    if (g_is64) {
        const long long* p = (const long long*)edges;
        s = (int)p[e]; d = (int)p[EE + e];
    } else {
        const int* p = (const int*)edges;
        s = p[e]; d = p[EE + e];
    }
    int pos = atomicAdd(&g_cursor[d], 1);
    g_src_sorted[pos] = s;
}

// ---------------- layer-1 aggregation: gather fp16 xH + fp16 hi/lo split --------
__global__ __launch_bounds__(128) void k_agg_x(
    const __half* __restrict__ xf, __half* __restrict__ mh, __half* __restrict__ ml)
{
    int tid = threadIdx.x, group = tid >> 4, lane = tid & 15;
    int node = blockIdx.x * 8 + group;
    if (node >= NN) return;
    int beg = g_offs[node], end = g_offs[node + 1];
    float acc[8] = {};
    int e = beg;
    for (; e + 1 < end; e += 2) {
        uint4 v0 = ((const uint4*)(xf + (size_t)g_src_sorted[e] * 128))[lane];
        uint4 v1 = ((const uint4*)(xf + (size_t)g_src_sorted[e + 1] * 128))[lane];
        const __half2* h0 = (const __half2*)&v0;
        const __half2* h1 = (const __half2*)&v1;
#pragma unroll
        for (int j = 0; j < 4; j++) {
            float2 f0 = __half22float2(h0[j]);
            float2 f1 = __half22float2(h1[j]);
            acc[2 * j]     += f0.x + f1.x;
            acc[2 * j + 1] += f0.y + f1.y;
        }
    }
    if (e < end) {
        uint4 v0 = ((const uint4*)(xf + (size_t)g_src_sorted[e] * 128))[lane];
        const __half2* h0 = (const __half2*)&v0;
#pragma unroll
        for (int j = 0; j < 4; j++) {
            float2 f0 = __half22float2(h0[j]);
            acc[2 * j] += f0.x; acc[2 * j + 1] += f0.y;
        }
    }
    float inv = 1.0f / fmaxf((float)(end - beg), 1.0f);
    __half hv[8], lv[8];
#pragma unroll
    for (int j = 0; j < 8; j++) {
        float o = acc[j] * inv;
        hv[j] = __float2half_rn(o);
        lv[j] = __float2half_rn(o - __half2float(hv[j]));
    }
    ((uint4*)(mh + (size_t)node * 128))[lane] = *(uint4*)hv;
    ((uint4*)(ml + (size_t)node * 128))[lane] = *(uint4*)lv;
}

// ---------------- post-aggregation (fp16 Zl gather) + fused BN stats ------------
__global__ __launch_bounds__(128) void k_agg_post2(
    const __half* __restrict__ zl, const float* __restrict__ zr, float* __restrict__ out)
{
    __shared__ float ss[256], sq[256];
    int tid = threadIdx.x;
    ss[tid] = 0.f; sq[tid] = 0.f; ss[tid + 128] = 0.f; sq[tid + 128] = 0.f;
    __syncthreads();
    int group = tid >> 5, lane = tid & 31;
    float ts[8] = {}, tq[8] = {};
    for (int node = blockIdx.x * 4 + group; node < NN; node += gridDim.x * 4) {
        int beg = g_offs[node], end = g_offs[node + 1];
        float acc[8] = {};
        int e = beg;
        for (; e + 1 < end; e += 2) {
            uint4 v0 = ((const uint4*)(zl + (size_t)g_src_sorted[e] * 256))[lane];
            uint4 v1 = ((const uint4*)(zl + (size_t)g_src_sorted[e + 1] * 256))[lane];
            const __half2* h0 = (const __half2*)&v0;
            const __half2* h1 = (const __half2*)&v1;
#pragma unroll
            for (int j = 0; j < 4; j++) {
                float2 f0 = __half22float2(h0[j]);
                float2 f1 = __half22float2(h1[j]);
                acc[2 * j]     += f0.x + f1.x;
                acc[2 * j + 1] += f0.y + f1.y;
            }
        }
        if (e < end) {
            uint4 v0 = ((const uint4*)(zl + (size_t)g_src_sorted[e] * 256))[lane];
            const __half2* h0 = (const __half2*)&v0;
#pragma unroll
            for (int j = 0; j < 4; j++) {
                float2 f0 = __half22float2(h0[j]);
                acc[2 * j] += f0.x; acc[2 * j + 1] += f0.y;
            }
        }
        float inv = 1.0f / fmaxf((float)(end - beg), 1.0f);
        float4 r0 = ((const float4*)(zr + (size_t)node * 256))[2 * lane];
        float4 r1 = ((const float4*)(zr + (size_t)node * 256))[2 * lane + 1];
        float o[8];
        o[0] = acc[0] * inv + r0.x; o[1] = acc[1] * inv + r0.y;
        o[2] = acc[2] * inv + r0.z; o[3] = acc[3] * inv + r0.w;
        o[4] = acc[4] * inv + r1.x; o[5] = acc[5] * inv + r1.y;
        o[6] = acc[6] * inv + r1.z; o[7] = acc[7] * inv + r1.w;
        ((float4*)(out + (size_t)node * 256))[2 * lane]     = make_float4(o[0], o[1], o[2], o[3]);
        ((float4*)(out + (size_t)node * 256))[2 * lane + 1] = make_float4(o[4], o[5], o[6], o[7]);
#pragma unroll
        for (int j = 0; j < 8; j++) { ts[j] += o[j]; tq[j] += o[j] * o[j]; }
    }
#pragma unroll
    for (int j = 0; j < 8; j++) {
        atomicAdd(&ss[lane * 8 + j], ts[j]);
        atomicAdd(&sq[lane * 8 + j], tq[j]);
    }
    __syncthreads();
    atomicAdd(&g_acc[tid],             (double)ss[tid]);
    atomicAdd(&g_acc[tid + 128],       (double)ss[tid + 128]);
    atomicAdd(&g_acc[256 + tid],       (double)sq[tid]);
    atomicAdd(&g_acc[256 + tid + 128], (double)sq[tid + 128]);
}

__global__ __launch_bounds__(128) void k_agg_post3(
    const __half* __restrict__ zl, const float* __restrict__ zr, float* __restrict__ out)
{
    __shared__ float ss[128], sq[128];
    int tid = threadIdx.x;
    ss[tid] = 0.f; sq[tid] = 0.f;
    __syncthreads();
    int group = tid >> 4, lane = tid & 15;
    float ts[8] = {}, tq[8] = {};
    for (int node = blockIdx.x * 8 + group; node < NN; node += gridDim.x * 8) {
        int beg = g_offs[node], end = g_offs[node + 1];
        float acc[8] = {};
        int e = beg;
        for (; e + 1 < end; e += 2) {
            uint4 v0 = ((const uint4*)(zl + (size_t)g_src_sorted[e] * 128))[lane];
            uint4 v1 = ((const uint4*)(zl + (size_t)g_src_sorted[e + 1] * 128))[lane];
            const __half2* h0 = (const __half2*)&v0;
            const __half2* h1 = (const __half2*)&v1;
#pragma unroll
            for (int j = 0; j < 4; j++) {
                float2 f0 = __half22float2(h0[j]);
                float2 f1 = __half22float2(h1[j]);
                acc[2 * j]     += f0.x + f1.x;
                acc[2 * j + 1] += f0.y + f1.y;
            }
        }
        if (e < end) {
            uint4 v0 = ((const uint4*)(zl + (size_t)g_src_sorted[e] * 128))[lane];
            const __half2* h0 = (const __half2*)&v0;
#pragma unroll
            for (int j = 0; j < 4; j++) {
                float2 f0 = __half22float2(h0[j]);
                acc[2 * j] += f0.x; acc[2 * j + 1] += f0.y;
            }
        }
        float inv = 1.0f / fmaxf((float)(end - beg), 1.0f);
        float4 r0 = ((const float4*)(zr + (size_t)node * 128))[2 * lane];
        float4 r1 = ((const float4*)(zr + (size_t)node * 128))[2 * lane + 1];
        float o[8];
        o[0] = acc[0] * inv + r0.x; o[1] = acc[1] * inv + r0.y;
        o[2] = acc[2] * inv + r0.z; o[3] = acc[3] * inv + r0.w;
        o[4] = acc[4] * inv + r1.x; o[5] = acc[5] * inv + r1.y;
        o[6] = acc[6] * inv + r1.z; o[7] = acc[7] * inv + r1.w;
        ((float4*)(out + (size_t)node * 128))[2 * lane]     = make_float4(o[0], o[1], o[2], o[3]);
        ((float4*)(out + (size_t)node * 128))[2 * lane + 1] = make_float4(o[4], o[5], o[6], o[7]);
#pragma unroll
        for (int j = 0; j < 8; j++) { ts[j] += o[j]; tq[j] += o[j] * o[j]; }
    }
#pragma unroll
    for (int j = 0; j < 8; j++) {
        atomicAdd(&ss[lane * 8 + j], ts[j]);
        atomicAdd(&sq[lane * 8 + j], tq[j]);
    }
    __syncthreads();
    atomicAdd(&g_acc[tid],       (double)ss[tid]);
    atomicAdd(&g_acc[256 + tid], (double)sq[tid]);
}

// ---------------- fp16 2-term mma.sync GEMM; 3-stage pipeline ------------------
// MODE 0: L1 dual (NSEG=4) + fused BN stats; MODE 1: L2 (x<2 -> Z); MODE 2: L3 (x==0 -> Z)
template <int DI, int NSEG, int MODE>
__global__ __launch_bounds__(256) void k_gemm_mma(
    const __half* __restrict__ A1h, const __half* __restrict__ A1l,
    const __half* __restrict__ A2h, const __half* __restrict__ A2l,
    const __half* __restrict__ B1, const __half* __restrict__ B2,
    float* __restrict__ C, __half* __restrict__ Z)
{
    constexpr int CH_PER_SEG = DI / 32;
    constexpr int NCH = NSEG * CH_PER_SEG;
    constexpr uint32_t STG = 20480;
    extern __shared__ __align__(128) char smem[];
    __shared__ float cs[128], cq[128];
    const uint32_t sbase = smem_u32(smem);
    const int tid = threadIdx.x;
    const int wid = tid >> 5, lane = tid & 31;
    const int wr = wid >> 2, wcn = wid & 3;
    const int rowBase = blockIdx.y * 128;   // M-tile (slow)
    const int colBase = blockIdx.x * 128;   // N-tile (fast -> A reuse)

    const __half* Asrc[4] = {A1h, A1l, A2h, A2l};
    const __half* Bsrc[4] = {B1, B1, B2, B2};

    const int lrow = tid >> 2;
    const int lcg  = tid & 3;
    const uint32_t sA0 = sbase + lrow * 80 + lcg * 16;
    const uint32_t sB0 = sbase + 10240 + lrow * 80 + lcg * 16;

    auto load = [&](int c) {
        const int s = c % 3;
        const int seg = c / CH_PER_SEG;
        const int kk = (c % CH_PER_SEG) * 32;
        const __half* Ap = Asrc[seg] + (size_t)rowBase * DI + kk + lcg * 8;
        const __half* Bp = Bsrc[seg] + (size_t)colBase * DI + kk + lcg * 8;
        const uint32_t so = s * STG;
        CP_ASYNC16(sA0 + so,        Ap + (size_t)lrow * DI);
        CP_ASYNC16(sA0 + so + 5120, Ap + (size_t)(lrow + 64) * DI);
        CP_ASYNC16(sB0 + so,        Bp + (size_t)lrow * DI);
        CP_ASYNC16(sB0 + so + 5120, Bp + (size_t)(lrow + 64) * DI);
        CP_COMMIT();
    };

    float acc[4][4][4] = {};
    const uint32_t aAddr = sbase + (wr * 64 + (lane & 15)) * 80 + (lane >> 4) * 16;
    const uint32_t bAddr = sbase + 10240 +
        (wcn * 32 + (lane & 7) + ((lane >> 4) << 3)) * 80 + ((lane >> 3) & 1) * 16;

    load(0);
    load(1);
    for (int c = 0; c < NCH; c++) {
        if (c + 1 < NCH)
            asm volatile("cp.async.wait_group 1;" ::: "memory");
        else
            asm volatile("cp.async.wait_group 0;" ::: "memory");
        __syncthreads();
        // all warps are past reading stage (c+2)%3 (read at iter c-1) -> safe to refill
        if (c + 2 < NCH) load(c + 2);
        const uint32_t so = (uint32_t)(c % 3) * STG;
#pragma unroll
        for (int kb = 0; kb < 2; kb++) {
            uint32_t afr[4][4], bfr[4][2];
#pragma unroll
            for (int mt = 0; mt < 4; mt++)
                LDSM4(afr[mt], aAddr + so + mt * (16 * 80) + kb * 32);
#pragma unroll
            for (int ntp = 0; ntp < 2; ntp++) {
                uint32_t r[4];
                LDSM4(r, bAddr + so + ntp * (16 * 80) + kb * 32);
                bfr[ntp * 2][0] = r[0]; bfr[ntp * 2][1] = r[1];
                bfr[ntp * 2 + 1][0] = r[2]; bfr[ntp * 2 + 1][1] = r[3];
            }
#pragma unroll
            for (int mt = 0; mt < 4; mt++)
#pragma unroll
                for (int nt = 0; nt < 4; nt++)
                    MMAF16(acc[mt][nt], afr[mt], bfr[nt]);
        }
    }

    // epilogue
    constexpr int STRIDE = (MODE == 2) ? 128 : 256;
    const bool isZ = (MODE == 1) ? (blockIdx.x < 2) : (MODE == 2 ? (blockIdx.x == 0) : false);
    const int cadj = (MODE == 0 || isZ) ? colBase : colBase - STRIDE;
#pragma unroll
    for (int mt = 0; mt < 4; mt++) {
        const int r0 = rowBase + wr * 64 + mt * 16 + (lane >> 2);
#pragma unroll
        for (int nt = 0; nt < 4; nt++) {
            const int cc = cadj + wcn * 32 + nt * 8 + (lane & 3) * 2;
            if (MODE != 0 && isZ) {
                if (r0 < NN)
                    *(__half2*)(Z + (size_t)r0 * STRIDE + cc) =
                        __floats2half2_rn(acc[mt][nt][0], acc[mt][nt][1]);
                if (r0 + 8 < NN)
                    *(__half2*)(Z + (size_t)(r0 + 8) * STRIDE + cc) =
                        __floats2half2_rn(acc[mt][nt][2], acc[mt][nt][3]);
            } else {
                if (r0 < NN)
                    *(float2*)(C + (size_t)r0 * STRIDE + cc) =
                        make_float2(acc[mt][nt][0], acc[mt][nt][1]);
                if (r0 + 8 < NN)
                    *(float2*)(C + (size_t)(r0 + 8) * STRIDE + cc) =
                        make_float2(acc[mt][nt][2], acc[mt][nt][3]);
            }
        }
    }

    if (MODE == 0) {
        if (tid < 128) { cs[tid] = 0.f; cq[tid] = 0.f; }
        __syncthreads();
#pragma unroll
        for (int nt = 0; nt < 4; nt++) {
            float s0 = 0.f, q0 = 0.f, s1 = 0.f, q1 = 0.f;
#pragma unroll
            for (int mt = 0; mt < 4; mt++) {
                float a0 = acc[mt][nt][0], a1 = acc[mt][nt][1];
                float a2 = acc[mt][nt][2], a3 = acc[mt][nt][3];
                s0 += a0 + a2; q0 += a0 * a0 + a2 * a2;
                s1 += a1 + a3; q1 += a1 * a1 + a3 * a3;
            }
            int cc = wcn * 32 + nt * 8 + (lane & 3) * 2;
            atomicAdd(&cs[cc], s0);     atomicAdd(&cq[cc], q0);
            atomicAdd(&cs[cc + 1], s1); atomicAdd(&cq[cc + 1], q1);
        }
        __syncthreads();
        if (tid < 128) {
            atomicAdd(&g_acc[colBase + tid],       (double)cs[tid]);
            atomicAdd(&g_acc[256 + colBase + tid], (double)cq[tid]);
        }
    }
}

// ---------------- BN finalize (single block; reads stats, self-zeroes) ----------
template <int D>
__global__ void k_finalize(const float* __restrict__ g, const float* __restrict__ b) {
    int c = threadIdx.x;  // launched with 256 threads always
    if (c < D) {
        double mu  = g_acc[c] / (double)NN;
        double var = g_acc[256 + c] / (double)NN - mu * mu;
        double rs  = 1.0 / sqrt(var + BN_EPS);
        double sc  = (double)g[c] * rs;
        g_scale[c] = (float)sc;
        g_shift[c] = (float)((double)b[c] - mu * sc);
    }
    g_acc[c] = 0.0;
    g_acc[256 + c] = 0.0;
}
// BN + ReLU -> fp16 hi/lo
template <int D>
__global__ void k_bn_hl(const float* __restrict__ in,
                        __half* __restrict__ outH, __half* __restrict__ outL) {
    int i = blockIdx.x * blockDim.x + threadIdx.x;
    int total4 = NN * D / 4;
    if (i >= total4) return;
    int c4 = (i & (D / 4 - 1)) * 4;
    float4 v  = ((const float4*)in)[i];
    float4 sc = *(const float4*)&g_scale[c4];
    float4 sh = *(const float4*)&g_shift[c4];
    float o[4];
    o[0] = fmaxf(v.x * sc.x + sh.x, 0.f);
    o[1] = fmaxf(v.y * sc.y + sh.y, 0.f);
    o[2] = fmaxf(v.z * sc.z + sh.z, 0.f);
    o[3] = fmaxf(v.w * sc.w + sh.w, 0.f);
    __half hv[4], lv[4];
#pragma unroll
    for (int q = 0; q < 4; q++) {
        hv[q] = __float2half_rn(o[q]);
        lv[q] = __float2half_rn(o[q] - __half2float(hv[q]));
    }
    *(uint2*)(outH + (size_t)i * 4) = *(uint2*)hv;
    *(uint2*)(outL + (size_t)i * 4) = *(uint2*)lv;
}

// fused BN + ReLU + classifier (layer 3): pre3 [N,128] -> out [N,15]
__global__ __launch_bounds__(256) void k_bn_cls(
    const float* __restrict__ pre3, const float* __restrict__ wc,
    const float* __restrict__ bc, float* __restrict__ out)
{
    __shared__ float4 wsh[NCLS * 32];
    __shared__ float  bsh[NCLS];
    int tid = threadIdx.x;
    for (int i = tid; i < NCLS * 32; i += 256) wsh[i] = ((const float4*)wc)[i];
    if (tid < NCLS) bsh[tid] = bc[tid];
    __syncthreads();
    int warp = tid >> 5, lane = tid & 31;
    int row = blockIdx.x * 8 + warp;
    if (row >= NN) return;
    float4 v  = ((const float4*)pre3)[(size_t)row * 32 + lane];
    float4 sc = *(const float4*)&g_scale[lane * 4];
    float4 sh = *(const float4*)&g_shift[lane * 4];
    float4 hv;
    hv.x = fmaxf(v.x * sc.x + sh.x, 0.f);
    hv.y = fmaxf(v.y * sc.y + sh.y, 0.f);
    hv.z = fmaxf(v.z * sc.z + sh.z, 0.f);
    hv.w = fmaxf(v.w * sc.w + sh.w, 0.f);
#pragma unroll
    for (int j = 0; j < NCLS; j++) {
        float4 w = wsh[j * 32 + lane];
        float p = hv.x * w.x + hv.y * w.y + hv.z * w.z + hv.w * w.w;
#pragma unroll
        for (int o = 16; o > 0; o >>= 1) p += __shfl_xor_sync(0xFFFFFFFFu, p, o);
        if (lane == 0) out[(size_t)row * NCLS + j] = p + bsh[j];
    }
}

// ---------------- driver --------------------------------------------------------
extern "C" void kernel_launch(void* const* d_in, const int* in_sizes, int n_in,
                              void* d_out, int out_size)
{
    const float* x     = (const float*)d_in[0];
    const void*  edges = d_in[1];
    const float* w1_l = (const float*)d_in[2];
    const float* w1_r = (const float*)d_in[4];
    const float* g1   = (const float*)d_in[5];
    const float* be1  = (const float*)d_in[6];
    const float* w2_l = (const float*)d_in[7];
    const float* w2_r = (const float*)d_in[9];
    const float* g2   = (const float*)d_in[10];
    const float* be2  = (const float*)d_in[11];
    const float* w3_l = (const float*)d_in[12];
    const float* w3_r = (const float*)d_in[14];
    const float* g3   = (const float*)d_in[15];
    const float* be3  = (const float*)d_in[16];
    const float* wc   = (const float*)d_in[17];
    const float* bc   = (const float*)d_in[18];
    float* out = (float*)d_out;

    static float *pre = nullptr, *pre2 = nullptr, *pre3 = nullptr;
    static __half *zl, *meanH, *meanL, *actH, *actL, *xH, *xL, *wbuf;
    const int GSMEM = 3 * 20480;  // 61,440 B dynamic
    if (!pre) {
        cudaGetSymbolAddress((void**)&pre,   g_pre);
        cudaGetSymbolAddress((void**)&pre2,  g_pre2);
        cudaGetSymbolAddress((void**)&pre3,  g_pre3);
        cudaGetSymbolAddress((void**)&zl,    g_zl);
        cudaGetSymbolAddress((void**)&meanH, g_meanH);
        cudaGetSymbolAddress((void**)&meanL, g_meanL);
        cudaGetSymbolAddress((void**)&actH,  g_actH);
        cudaGetSymbolAddress((void**)&actL,  g_actL);
        cudaGetSymbolAddress((void**)&xH,    g_xH);
        cudaGetSymbolAddress((void**)&xL,    g_xL);
        cudaGetSymbolAddress((void**)&wbuf,  g_w);
        cudaFuncSetAttribute(k_gemm_mma<128, 4, 0>,
                             cudaFuncAttributeMaxDynamicSharedMemorySize, GSMEM);
        cudaFuncSetAttribute(k_gemm_mma<256, 2, 1>,
                             cudaFuncAttributeMaxDynamicSharedMemorySize, GSMEM);
        cudaFuncSetAttribute(k_gemm_mma<256, 2, 2>,
                             cudaFuncAttributeMaxDynamicSharedMemorySize, GSMEM);
    }
    // weight layout (fp16): W1l@0, W1r@32768, W2stk@65536, W3stk@196608
    __half* W1l = wbuf;
    __half* W1r = wbuf + 32768;
    __half* W2  = wbuf + 65536;
    __half* W3  = wbuf + 196608;

    const int EB = (EE + 255) / 256;
    const int NB = (NN + 255) / 256;

    // ---- CSR build (scan2 merged into scan3) ----
    k_zero_cnt<<<NB, 256>>>(edges);
    k_hist<<<EB, 256>>>(edges);
    k_scan1<<<(NN + 1023) / 1024, 1024>>>();
    k_scan3<<<NB, 256>>>();
    k_fill<<<EB, 256>>>(edges);

    // ---- weight + x conversions (fp16), single launch ----
    k_convert<<<1024 + (NN * 128 + 255) / 256, 256>>>(w1_l, w1_r, w2_l, w2_r, w3_l, w3_r,
                                                      wbuf, x, xH, xL);

    const int MT = NN_PAD / 128;  // 782

    // ---- layer 1: pre-agg (fp16 gather) + dual GEMM (stats fused) ----
    k_agg_x<<<(NN + 7) / 8, 128>>>(xH, meanH, meanL);
    k_gemm_mma<128, 4, 0><<<dim3(2, MT), 256, GSMEM>>>(meanH, meanL, xH, xL,
                                                       W1l, W1r, pre, nullptr);
    k_finalize<C1><<<1, 256>>>(g1, be1);
    k_bn_hl<C1><<<(NN * C1 / 4 + 255) / 256, 256>>>(pre, actH, actL);

    // ---- layer 2: single-A GEMM (DO=512) -> fp16 Zl + fp32 Zr; post-agg ----
    k_gemm_mma<256, 2, 1><<<dim3(4, MT), 256, GSMEM>>>(actH, actL, nullptr, nullptr,
                                                       W2, nullptr, pre, zl);
    k_agg_post2<<<1024, 128>>>(zl, pre, pre2);
    k_finalize<C1><<<1, 256>>>(g2, be2);
    k_bn_hl<C1><<<(NN * C1 / 4 + 255) / 256, 256>>>(pre2, actH, actL);

    // ---- layer 3: single-A GEMM (DO=256) -> fp16 Zl + fp32 Zr; post-agg ----
    k_gemm_mma<256, 2, 2><<<dim3(2, MT), 256, GSMEM>>>(actH, actL, nullptr, nullptr,
                                                       W3, nullptr, pre, zl);
    k_agg_post3<<<1024, 128>>>(zl, pre, pre3);
    k_finalize<C3><<<1, 256>>>(g3, be3);

    // ---- fused BN + ReLU + classifier ----
    k_bn_cls<<<(NN + 7) / 8, 256>>>(pre3, wc, bc, out);
}